// round 8
// baseline (speedup 1.0000x reference)
#include <cuda_runtime.h>

#define PLANE (128*128)
#define VOL (128*128*128)

// Scratch (device globals — no allocation allowed)
__device__ float g_H[8*VOL];    // 64 MB
__device__ float g_A[8*VOL];    // 64 MB
__device__ float g_W[27*VOL];   // 226 MB: adaptive weights, 27 fp32 tap-planes
__device__ float g_F[VOL];      // 8 MB single-channel ping buffer

typedef unsigned long long u64;

// ---- packed f32x2 helpers (FFMA2 is PTX-only on sm_103a) ----
__device__ __forceinline__ u64 pack2(float lo, float hi){
  u64 r;
  asm("mov.b64 %0, {%1, %2};" : "=l"(r) : "f"(lo), "f"(hi));
  return r;
}
__device__ __forceinline__ void unpack2(float& lo, float& hi, u64 v){
  asm("mov.b64 {%0, %1}, %2;" : "=f"(lo), "=f"(hi) : "l"(v));
}
__device__ __forceinline__ void fma2(u64& d, u64 a, u64 b){
  asm("fma.rn.f32x2 %0, %1, %2, %0;" : "+l"(d) : "l"(a), "l"(b));
}

// ============================================================================
// 3x3x3 conv, CIN=8, SAME zero padding, channel-planar layout.
// Thread = adjacent w-pair (w0 even). Block 128 threads covers 2 h-rows.
// Grid: (64 h-pairs, 128 d). Weights: SMEM ulonglong2 (4 packed per LDS.128).
// Output-channel pairs accumulate in f32x2.
// NORM path writes the L1-normalized 27-tap field as fp32 float2 per plane.
// ============================================================================
template<int COUT, bool RELU, bool NORM>
__global__ void __launch_bounds__(128)
conv3d_k(const float* __restrict__ x, const float* __restrict__ wgt,
         const float* __restrict__ bias, float* __restrict__ out)
{
  constexpr int CPH = (COUT + 3) / 4;   // u128 weight groups (4 out-channels)
  constexpr int CP  = 2*CPH;            // u64 accumulator pairs
  __shared__ ulonglong2 wp[8*27*CPH];
  const int tid = threadIdx.x;
  const int h  = 2*blockIdx.x + (tid >> 6);
  const int w0 = (tid & 63)*2;
  const int d  = blockIdx.y;

  for (int i = tid; i < 8*27*CPH; i += 128){
    int p2 = i % CPH; int rest = i / CPH; int t = rest % 27; int ci = rest / 27;
    float c0 = (4*p2+0 < COUT) ? wgt[((4*p2+0)*8 + ci)*27 + t] : 0.f;
    float c1 = (4*p2+1 < COUT) ? wgt[((4*p2+1)*8 + ci)*27 + t] : 0.f;
    float c2 = (4*p2+2 < COUT) ? wgt[((4*p2+2)*8 + ci)*27 + t] : 0.f;
    float c3 = (4*p2+3 < COUT) ? wgt[((4*p2+3)*8 + ci)*27 + t] : 0.f;
    wp[i] = make_ulonglong2(pack2(c0,c1), pack2(c2,c3));
  }
  __syncthreads();

  u64 acc0[CP], acc1[CP];
  #pragma unroll
  for (int p = 0; p < CP; p++){
    float blo = (bias && 2*p   < COUT) ? bias[2*p]   : 0.f;
    float bhi = (bias && 2*p+1 < COUT) ? bias[2*p+1] : 0.f;
    acc0[p] = pack2(blo, bhi);
    acc1[p] = acc0[p];
  }

  const bool pd[3] = { d > 0, true, d < 127 };
  const bool ph[3] = { h > 0, true, h < 127 };
  const bool pa = w0 > 0, pe = w0 < 126;
  const int base = d*PLANE + h*128 + w0;

  #pragma unroll 1
  for (int ci = 0; ci < 8; ci++){
    const float* b = x + ci*VOL + base;
    const ulonglong2* wci = wp + ci*27*CPH;
    #pragma unroll
    for (int i = 0; i < 3; i++){
      #pragma unroll
      for (int j = 0; j < 3; j++){
        const int OFF = (i-1)*PLANE + (j-1)*128;
        const bool vr = pd[i] && ph[j];
        float2 bc = make_float2(0.f, 0.f);
        float av = 0.f, dv = 0.f;
        if (vr)       bc = *reinterpret_cast<const float2*>(b + OFF);
        if (vr && pa) av = __ldg(b + OFF - 1);
        if (vr && pe) dv = __ldg(b + OFF + 2);
        u64 va = pack2(av,av), vb = pack2(bc.x,bc.x), vc = pack2(bc.y,bc.y), vd = pack2(dv,dv);
        const ulonglong2* wt = wci + (i*9 + j*3)*CPH;
        #pragma unroll
        for (int k = 0; k < 3; k++){
          u64 q0 = (k==0) ? va : (k==1) ? vb : vc;   // voxel w0
          u64 q1 = (k==0) ? vb : (k==1) ? vc : vd;   // voxel w0+1
          #pragma unroll
          for (int p2 = 0; p2 < CPH; p2++){
            ulonglong2 wv = wt[k*CPH + p2];
            fma2(acc0[2*p2  ], q0, wv.x);
            fma2(acc0[2*p2+1], q0, wv.y);
            fma2(acc1[2*p2  ], q1, wv.x);
            fma2(acc1[2*p2+1], q1, wv.y);
          }
        }
      }
    }
  }

  float r0[2*CP], r1[2*CP];
  #pragma unroll
  for (int p = 0; p < CP; p++){
    unpack2(r0[2*p], r0[2*p+1], acc0[p]);
    unpack2(r1[2*p], r1[2*p+1], acc1[p]);
  }
  if (RELU){
    #pragma unroll
    for (int c = 0; c < COUT; c++){ r0[c] = fmaxf(r0[c],0.f); r1[c] = fmaxf(r1[c],0.f); }
  }

  if (NORM){
    float s0 = 0.f, s1 = 0.f;
    #pragma unroll
    for (int c = 0; c < COUT; c++){ s0 += fabsf(r0[c]); s1 += fabsf(r1[c]); }
    float i0 = 1.f / fmaxf(s0, 1e-12f);
    float i1 = 1.f / fmaxf(s1, 1e-12f);
    #pragma unroll
    for (int c = 0; c < COUT; c++){
      float2 o; o.x = r0[c]*i0; o.y = r1[c]*i1;
      *reinterpret_cast<float2*>(out + c*VOL + base) = o;
    }
  } else {
    #pragma unroll
    for (int c = 0; c < COUT; c++){
      float2 o; o.x = r0[c]; o.y = r1[c];
      *reinterpret_cast<float2*>(out + c*VOL + base) = o;
    }
  }
}

// ============================================================================
// Adaptive conv: out[c,v] = sum_t w[t,v] * x[c, nbr_t(v)].
// Thread = adjacent w-pair; per-voxel fp32 weights (27 tap-planes) loaded as
// float2 once, reused across all C channels. Predicated const-offset LDG.
// ============================================================================
template<int C, bool TANH>
__global__ void __launch_bounds__(256)
adapt_k(const float* __restrict__ x, const float* __restrict__ w27,
        float* __restrict__ out)
{
  const int v0 = (blockIdx.x*256 + threadIdx.x)*2;
  const int d = v0 >> 14, h = (v0 >> 7) & 127, w0 = v0 & 127;

  float wv0[27], wv1[27];
  #pragma unroll
  for (int t = 0; t < 27; t++){
    float2 q = *reinterpret_cast<const float2*>(w27 + t*VOL + v0);
    wv0[t] = q.x; wv1[t] = q.y;
  }

  const bool pd[3] = { d > 0, true, d < 127 };
  const bool ph[3] = { h > 0, true, h < 127 };
  const bool pa = w0 > 0, pe = w0 < 126;

  #pragma unroll 1
  for (int c = 0; c < C; c++){
    const float* b = x + c*VOL + v0;
    float a0 = 0.f, a1 = 0.f;
    #pragma unroll
    for (int i = 0; i < 3; i++){
      #pragma unroll
      for (int j = 0; j < 3; j++){
        const int OFF = (i-1)*PLANE + (j-1)*128;
        const bool vr = pd[i] && ph[j];
        float2 bc = make_float2(0.f, 0.f);
        float av = 0.f, dv = 0.f;
        if (vr)       bc = *reinterpret_cast<const float2*>(b + OFF);
        if (vr && pa) av = __ldg(b + OFF - 1);
        if (vr && pe) dv = __ldg(b + OFF + 2);
        const int t = i*9 + j*3;
        a0 = fmaf(wv0[t], av,   fmaf(wv0[t+1], bc.x, fmaf(wv0[t+2], bc.y, a0)));
        a1 = fmaf(wv1[t], bc.x, fmaf(wv1[t+1], bc.y, fmaf(wv1[t+2], dv,   a1)));
      }
    }
    float2 o;
    o.x = TANH ? tanhf(a0) : a0;
    o.y = TANH ? tanhf(a1) : a1;
    *reinterpret_cast<float2*>(out + c*VOL + v0) = o;
  }
}

extern "C" void kernel_launch(void* const* d_in, const int* in_sizes, int n_in,
                              void* d_out, int out_size)
{
  const float* x    = (const float*)d_in[0];
  const float* a1w1 = (const float*)d_in[1];
  const float* a1b1 = (const float*)d_in[2];
  const float* a1w2 = (const float*)d_in[3];
  const float* a2w1 = (const float*)d_in[4];
  const float* a2b1 = (const float*)d_in[5];
  const float* a2w2 = (const float*)d_in[6];
  const float* a3w1 = (const float*)d_in[7];
  const float* a3b1 = (const float*)d_in[8];
  const float* a3w2 = (const float*)d_in[9];
  const float* midw = (const float*)d_in[10];
  const float* midb = (const float*)d_in[11];
  const float* outw = (const float*)d_in[12];
  const float* outb = (const float*)d_in[13];
  float* y = (float*)d_out;

  float *H, *A, *W, *F;
  cudaGetSymbolAddress((void**)&H, g_H);
  cudaGetSymbolAddress((void**)&A, g_A);
  cudaGetSymbolAddress((void**)&W, g_W);
  cudaGetSymbolAddress((void**)&F, g_F);

  dim3 gc(64, 128), bc(128);        // conv: h-pair x d; thread = w-pair
  dim3 ga(VOL/512), ba(256);        // adapt: thread = w-pair

  // ---- adaptive block 1 (input x) ----
  conv3d_k<8,  true,  false><<<gc,bc>>>(x, a1w1, a1b1, H);     // h1
  conv3d_k<27, false, true ><<<gc,bc>>>(H, a1w2, nullptr, W);  // weight field
  adapt_k<8, false><<<ga,ba>>>(x, W, A);
  adapt_k<8, false><<<ga,ba>>>(A, W, H);
  adapt_k<8, false><<<ga,ba>>>(H, W, A);                       // block1 out = A

  // ---- mid conv ----
  conv3d_k<8, false, false><<<gc,bc>>>(A, midw, midb, H);      // mid = H

  // ---- adaptive block 2 (input mid) ----
  conv3d_k<8,  true,  false><<<gc,bc>>>(H, a2w1, a2b1, A);     // h2
  conv3d_k<27, false, true ><<<gc,bc>>>(A, a2w2, nullptr, W);
  adapt_k<8, false><<<ga,ba>>>(H, W, A);
  adapt_k<8, false><<<ga,ba>>>(A, W, H);
  adapt_k<8, false><<<ga,ba>>>(H, W, A);                       // mid2 = A

  // ---- out conv + adaptive block 3 (weights from mid2, data 1-channel) ----
  conv3d_k<1, false, false><<<gc,bc>>>(A, outw, outb, F);      // final (1ch)
  conv3d_k<8, true,  false><<<gc,bc>>>(A, a3w1, a3b1, H);      // h3 from mid2
  conv3d_k<27, false, true ><<<gc,bc>>>(H, a3w2, nullptr, W);
  adapt_k<1, false><<<ga,ba>>>(F, W, y);
  adapt_k<1, false><<<ga,ba>>>(y, W, F);
  adapt_k<1, true ><<<ga,ba>>>(F, W, y);                       // + tanh
}

// round 10
// speedup vs baseline: 1.0703x; 1.0703x over previous
#include <cuda_runtime.h>

#define PLANE (128*128)
#define VOL (128*128*128)

// Scratch (device globals — no allocation allowed)
__device__ float g_H[8*VOL];    // 64 MB
__device__ float g_A[8*VOL];    // 64 MB
__device__ float g_W[27*VOL];   // 226 MB: adaptive weights, 27 fp32 tap-planes
__device__ float g_F[VOL];      // 8 MB single-channel ping buffer

typedef unsigned long long u64;

// ---- packed f32x2 helpers (FFMA2 is PTX-only on sm_103a) ----
__device__ __forceinline__ u64 pack2(float lo, float hi){
  u64 r;
  asm("mov.b64 %0, {%1, %2};" : "=l"(r) : "f"(lo), "f"(hi));
  return r;
}
__device__ __forceinline__ void unpack2(float& lo, float& hi, u64 v){
  asm("mov.b64 {%0, %1}, %2;" : "=f"(lo), "=f"(hi) : "l"(v));
}
__device__ __forceinline__ void fma2(u64& d, u64 a, u64 b){
  asm("fma.rn.f32x2 %0, %1, %2, %0;" : "+l"(d) : "l"(a), "l"(b));
}

// ============================================================================
// 3x3x3 conv, CIN=8, SAME zero padding, channel-planar layout. (R8 version)
// Thread = adjacent w-pair; weights in SMEM as ulonglong2 (uniform-address
// LDS.128 broadcast); output-channel pairs accumulate in f32x2.
// ============================================================================
template<int COUT, bool RELU, bool NORM>
__global__ void __launch_bounds__(128)
conv3d_k(const float* __restrict__ x, const float* __restrict__ wgt,
         const float* __restrict__ bias, float* __restrict__ out)
{
  constexpr int CPH = (COUT + 3) / 4;
  constexpr int CP  = 2*CPH;
  __shared__ ulonglong2 wp[8*27*CPH];
  const int tid = threadIdx.x;
  const int h  = 2*blockIdx.x + (tid >> 6);
  const int w0 = (tid & 63)*2;
  const int d  = blockIdx.y;

  for (int i = tid; i < 8*27*CPH; i += 128){
    int p2 = i % CPH; int rest = i / CPH; int t = rest % 27; int ci = rest / 27;
    float c0 = (4*p2+0 < COUT) ? wgt[((4*p2+0)*8 + ci)*27 + t] : 0.f;
    float c1 = (4*p2+1 < COUT) ? wgt[((4*p2+1)*8 + ci)*27 + t] : 0.f;
    float c2 = (4*p2+2 < COUT) ? wgt[((4*p2+2)*8 + ci)*27 + t] : 0.f;
    float c3 = (4*p2+3 < COUT) ? wgt[((4*p2+3)*8 + ci)*27 + t] : 0.f;
    wp[i] = make_ulonglong2(pack2(c0,c1), pack2(c2,c3));
  }
  __syncthreads();

  u64 acc0[CP], acc1[CP];
  #pragma unroll
  for (int p = 0; p < CP; p++){
    float blo = (bias && 2*p   < COUT) ? bias[2*p]   : 0.f;
    float bhi = (bias && 2*p+1 < COUT) ? bias[2*p+1] : 0.f;
    acc0[p] = pack2(blo, bhi);
    acc1[p] = acc0[p];
  }

  const bool pd[3] = { d > 0, true, d < 127 };
  const bool ph[3] = { h > 0, true, h < 127 };
  const bool pa = w0 > 0, pe = w0 < 126;
  const int base = d*PLANE + h*128 + w0;

  #pragma unroll 1
  for (int ci = 0; ci < 8; ci++){
    const float* b = x + ci*VOL + base;
    const ulonglong2* wci = wp + ci*27*CPH;
    #pragma unroll
    for (int i = 0; i < 3; i++){
      #pragma unroll
      for (int j = 0; j < 3; j++){
        const int OFF = (i-1)*PLANE + (j-1)*128;
        const bool vr = pd[i] && ph[j];
        float2 bc = make_float2(0.f, 0.f);
        float av = 0.f, dv = 0.f;
        if (vr)       bc = *reinterpret_cast<const float2*>(b + OFF);
        if (vr && pa) av = __ldg(b + OFF - 1);
        if (vr && pe) dv = __ldg(b + OFF + 2);
        u64 va = pack2(av,av), vb = pack2(bc.x,bc.x), vc = pack2(bc.y,bc.y), vd = pack2(dv,dv);
        const ulonglong2* wt = wci + (i*9 + j*3)*CPH;
        #pragma unroll
        for (int k = 0; k < 3; k++){
          u64 q0 = (k==0) ? va : (k==1) ? vb : vc;
          u64 q1 = (k==0) ? vb : (k==1) ? vc : vd;
          #pragma unroll
          for (int p2 = 0; p2 < CPH; p2++){
            ulonglong2 wv = wt[k*CPH + p2];
            fma2(acc0[2*p2  ], q0, wv.x);
            fma2(acc0[2*p2+1], q0, wv.y);
            fma2(acc1[2*p2  ], q1, wv.x);
            fma2(acc1[2*p2+1], q1, wv.y);
          }
        }
      }
    }
  }

  float r0[2*CP], r1[2*CP];
  #pragma unroll
  for (int p = 0; p < CP; p++){
    unpack2(r0[2*p], r0[2*p+1], acc0[p]);
    unpack2(r1[2*p], r1[2*p+1], acc1[p]);
  }
  if (RELU){
    #pragma unroll
    for (int c = 0; c < COUT; c++){ r0[c] = fmaxf(r0[c],0.f); r1[c] = fmaxf(r1[c],0.f); }
  }

  if (NORM){
    float s0 = 0.f, s1 = 0.f;
    #pragma unroll
    for (int c = 0; c < COUT; c++){ s0 += fabsf(r0[c]); s1 += fabsf(r1[c]); }
    float i0 = 1.f / fmaxf(s0, 1e-12f);
    float i1 = 1.f / fmaxf(s1, 1e-12f);
    #pragma unroll
    for (int c = 0; c < COUT; c++){
      float2 o; o.x = r0[c]*i0; o.y = r1[c]*i1;
      *reinterpret_cast<float2*>(out + c*VOL + base) = o;
    }
  } else {
    #pragma unroll
    for (int c = 0; c < COUT; c++){
      float2 o; o.x = r0[c]; o.y = r1[c];
      *reinterpret_cast<float2*>(out + c*VOL + base) = o;
    }
  }
}

// ============================================================================
// Adaptive conv, SMEM-tiled: out[c,v] = sum_t w[t,v] * x[c, nbr_t(v)].
// CTA = 2 h-rows x 128 w of one d-slice. SMEM tile [C][3d][4h][128w]
// (48 KB for C=8), filled once with float4 loads (no div/mod in fill),
// one sync, then pure LDS+FMA. w=+-1 halo is always out-of-volume for a
// full-width row -> predicated zero, no storage.
// 27 per-voxel fp32 weights in registers, reused across channels.
// ============================================================================
template<int C, bool TANH>
__global__ void __launch_bounds__(256)
adapt_k(const float* __restrict__ x, const float* __restrict__ w27,
        float* __restrict__ out)
{
  constexpr int ROWS = C*12;                  // C * 3d * 4h rows of 128 floats
  __shared__ float tile[ROWS*128];

  const int tid = threadIdx.x;
  const int h0 = 2*blockIdx.x;
  const int d  = blockIdx.y;

  // ---- fill: ROWS rows of 128 floats, 8 rows per pass (32 float4-lanes each)
  {
    const int sub  = tid >> 5;        // 0..7  (row within pass)
    const int lane = tid & 31;        // float4 column
    #pragma unroll
    for (int it = 0; it < (ROWS + 7)/8; it++){
      const int row = it*8 + sub;
      if (ROWS % 8 == 0 || row < ROWS){
        const int c  = (row*43) >> 9;           // row/12 for row<96
        const int rm = row - c*12;
        const int di = rm >> 2;                 // 0..2
        const int hi = rm & 3;                  // 0..3
        const int dd = d + di - 1;
        const int hh = h0 + hi - 1;
        float4 v = make_float4(0.f,0.f,0.f,0.f);
        if ((unsigned)dd < 128u && (unsigned)hh < 128u)
          v = *reinterpret_cast<const float4*>(x + c*VOL + (dd*128 + hh)*128 + lane*4);
        *reinterpret_cast<float4*>(tile + row*128 + lane*4) = v;
      }
    }
  }

  const int hs = tid >> 7;            // 0/1: which h row
  const int w  = tid & 127;
  const int idx = d*PLANE + (h0+hs)*128 + w;

  float wv[27];
  #pragma unroll
  for (int t = 0; t < 27; t++) wv[t] = __ldg(w27 + t*VOL + idx);

  __syncthreads();

  const bool wa = (w > 0), we = (w < 127);

  #pragma unroll 1
  for (int c = 0; c < C; c++){
    float s0 = 0.f, s1 = 0.f, s2 = 0.f;
    #pragma unroll
    for (int i = 0; i < 3; i++){
      #pragma unroll
      for (int j = 0; j < 3; j++){
        const float* rp = tile + ((c*12 + i*4 + hs + j)*128) + w;
        const int t = i*9 + j*3;
        float va = 0.f, vc = 0.f;
        if (wa) va = rp[-1];
        if (we) vc = rp[ 1];
        s0 = fmaf(wv[t  ], va,    s0);
        s1 = fmaf(wv[t+1], rp[0], s1);
        s2 = fmaf(wv[t+2], vc,    s2);
      }
    }
    float acc = s0 + s1 + s2;
    out[c*VOL + idx] = TANH ? tanhf(acc) : acc;
  }
}

extern "C" void kernel_launch(void* const* d_in, const int* in_sizes, int n_in,
                              void* d_out, int out_size)
{
  const float* x    = (const float*)d_in[0];
  const float* a1w1 = (const float*)d_in[1];
  const float* a1b1 = (const float*)d_in[2];
  const float* a1w2 = (const float*)d_in[3];
  const float* a2w1 = (const float*)d_in[4];
  const float* a2b1 = (const float*)d_in[5];
  const float* a2w2 = (const float*)d_in[6];
  const float* a3w1 = (const float*)d_in[7];
  const float* a3b1 = (const float*)d_in[8];
  const float* a3w2 = (const float*)d_in[9];
  const float* midw = (const float*)d_in[10];
  const float* midb = (const float*)d_in[11];
  const float* outw = (const float*)d_in[12];
  const float* outb = (const float*)d_in[13];
  float* y = (float*)d_out;

  float *H, *A, *W, *F;
  cudaGetSymbolAddress((void**)&H, g_H);
  cudaGetSymbolAddress((void**)&A, g_A);
  cudaGetSymbolAddress((void**)&W, g_W);
  cudaGetSymbolAddress((void**)&F, g_F);

  dim3 gc(64, 128), bc(128);        // conv: h-pair x d; thread = w-pair
  dim3 ga(64, 128), ba(256);        // adapt: h-pair x d; thread = voxel

  // ---- adaptive block 1 (input x) ----
  conv3d_k<8,  true,  false><<<gc,bc>>>(x, a1w1, a1b1, H);     // h1
  conv3d_k<27, false, true ><<<gc,bc>>>(H, a1w2, nullptr, W);  // weight field
  adapt_k<8, false><<<ga,ba>>>(x, W, A);
  adapt_k<8, false><<<ga,ba>>>(A, W, H);
  adapt_k<8, false><<<ga,ba>>>(H, W, A);                       // block1 out = A

  // ---- mid conv ----
  conv3d_k<8, false, false><<<gc,bc>>>(A, midw, midb, H);      // mid = H

  // ---- adaptive block 2 (input mid) ----
  conv3d_k<8,  true,  false><<<gc,bc>>>(H, a2w1, a2b1, A);     // h2
  conv3d_k<27, false, true ><<<gc,bc>>>(A, a2w2, nullptr, W);
  adapt_k<8, false><<<ga,ba>>>(H, W, A);
  adapt_k<8, false><<<ga,ba>>>(A, W, H);
  adapt_k<8, false><<<ga,ba>>>(H, W, A);                       // mid2 = A

  // ---- out conv + adaptive block 3 (weights from mid2, data 1-channel) ----
  conv3d_k<1, false, false><<<gc,bc>>>(A, outw, outb, F);      // final (1ch)
  conv3d_k<8, true,  false><<<gc,bc>>>(A, a3w1, a3b1, H);      // h3 from mid2
  conv3d_k<27, false, true ><<<gc,bc>>>(H, a3w2, nullptr, W);
  adapt_k<1, false><<<ga,ba>>>(F, W, y);
  adapt_k<1, false><<<ga,ba>>>(y, W, F);
  adapt_k<1, true ><<<ga,ba>>>(F, W, y);                       // + tanh
}

// round 11
// speedup vs baseline: 1.1813x; 1.1037x over previous
#include <cuda_runtime.h>

#define PLANE (128*128)
#define VOL (128*128*128)

// Scratch (device globals — no allocation allowed)
__device__ float g_H[8*VOL];    // 64 MB
__device__ float g_A[8*VOL];    // 64 MB
__device__ float g_W[27*VOL];   // 226 MB: adaptive weights, 27 fp32 tap-planes
__device__ float g_F[VOL];      // 8 MB single-channel ping buffer

typedef unsigned long long u64;

// ---- packed f32x2 helpers (FFMA2 is PTX-only on sm_103a) ----
__device__ __forceinline__ u64 pack2(float lo, float hi){
  u64 r;
  asm("mov.b64 %0, {%1, %2};" : "=l"(r) : "f"(lo), "f"(hi));
  return r;
}
__device__ __forceinline__ void unpack2(float& lo, float& hi, u64 v){
  asm("mov.b64 {%0, %1}, %2;" : "=f"(lo), "=f"(hi) : "l"(v));
}
__device__ __forceinline__ void fma2(u64& d, u64 a, u64 b){
  asm("fma.rn.f32x2 %0, %1, %2, %0;" : "+l"(d) : "l"(a), "l"(b));
}

// ============================================================================
// 3x3x3 conv, CIN=8, SAME zero padding, channel-planar layout. (R10 version)
// Thread = adjacent w-pair; weights in SMEM as ulonglong2 (uniform-address
// LDS.128 broadcast); output-channel pairs accumulate in f32x2.
// ============================================================================
template<int COUT, bool RELU, bool NORM>
__global__ void __launch_bounds__(128)
conv3d_k(const float* __restrict__ x, const float* __restrict__ wgt,
         const float* __restrict__ bias, float* __restrict__ out)
{
  constexpr int CPH = (COUT + 3) / 4;
  constexpr int CP  = 2*CPH;
  __shared__ ulonglong2 wp[8*27*CPH];
  const int tid = threadIdx.x;
  const int h  = 2*blockIdx.x + (tid >> 6);
  const int w0 = (tid & 63)*2;
  const int d  = blockIdx.y;

  for (int i = tid; i < 8*27*CPH; i += 128){
    int p2 = i % CPH; int rest = i / CPH; int t = rest % 27; int ci = rest / 27;
    float c0 = (4*p2+0 < COUT) ? wgt[((4*p2+0)*8 + ci)*27 + t] : 0.f;
    float c1 = (4*p2+1 < COUT) ? wgt[((4*p2+1)*8 + ci)*27 + t] : 0.f;
    float c2 = (4*p2+2 < COUT) ? wgt[((4*p2+2)*8 + ci)*27 + t] : 0.f;
    float c3 = (4*p2+3 < COUT) ? wgt[((4*p2+3)*8 + ci)*27 + t] : 0.f;
    wp[i] = make_ulonglong2(pack2(c0,c1), pack2(c2,c3));
  }
  __syncthreads();

  u64 acc0[CP], acc1[CP];
  #pragma unroll
  for (int p = 0; p < CP; p++){
    float blo = (bias && 2*p   < COUT) ? bias[2*p]   : 0.f;
    float bhi = (bias && 2*p+1 < COUT) ? bias[2*p+1] : 0.f;
    acc0[p] = pack2(blo, bhi);
    acc1[p] = acc0[p];
  }

  const bool pd[3] = { d > 0, true, d < 127 };
  const bool ph[3] = { h > 0, true, h < 127 };
  const bool pa = w0 > 0, pe = w0 < 126;
  const int base = d*PLANE + h*128 + w0;

  #pragma unroll 1
  for (int ci = 0; ci < 8; ci++){
    const float* b = x + ci*VOL + base;
    const ulonglong2* wci = wp + ci*27*CPH;
    #pragma unroll
    for (int i = 0; i < 3; i++){
      #pragma unroll
      for (int j = 0; j < 3; j++){
        const int OFF = (i-1)*PLANE + (j-1)*128;
        const bool vr = pd[i] && ph[j];
        float2 bc = make_float2(0.f, 0.f);
        float av = 0.f, dv = 0.f;
        if (vr)       bc = *reinterpret_cast<const float2*>(b + OFF);
        if (vr && pa) av = __ldg(b + OFF - 1);
        if (vr && pe) dv = __ldg(b + OFF + 2);
        u64 va = pack2(av,av), vb = pack2(bc.x,bc.x), vc = pack2(bc.y,bc.y), vd = pack2(dv,dv);
        const ulonglong2* wt = wci + (i*9 + j*3)*CPH;
        #pragma unroll
        for (int k = 0; k < 3; k++){
          u64 q0 = (k==0) ? va : (k==1) ? vb : vc;
          u64 q1 = (k==0) ? vb : (k==1) ? vc : vd;
          #pragma unroll
          for (int p2 = 0; p2 < CPH; p2++){
            ulonglong2 wv = wt[k*CPH + p2];
            fma2(acc0[2*p2  ], q0, wv.x);
            fma2(acc0[2*p2+1], q0, wv.y);
            fma2(acc1[2*p2  ], q1, wv.x);
            fma2(acc1[2*p2+1], q1, wv.y);
          }
        }
      }
    }
  }

  float r0[2*CP], r1[2*CP];
  #pragma unroll
  for (int p = 0; p < CP; p++){
    unpack2(r0[2*p], r0[2*p+1], acc0[p]);
    unpack2(r1[2*p], r1[2*p+1], acc1[p]);
  }
  if (RELU){
    #pragma unroll
    for (int c = 0; c < COUT; c++){ r0[c] = fmaxf(r0[c],0.f); r1[c] = fmaxf(r1[c],0.f); }
  }

  if (NORM){
    float s0 = 0.f, s1 = 0.f;
    #pragma unroll
    for (int c = 0; c < COUT; c++){ s0 += fabsf(r0[c]); s1 += fabsf(r1[c]); }
    float i0 = 1.f / fmaxf(s0, 1e-12f);
    float i1 = 1.f / fmaxf(s1, 1e-12f);
    #pragma unroll
    for (int c = 0; c < COUT; c++){
      float2 o; o.x = r0[c]*i0; o.y = r1[c]*i1;
      *reinterpret_cast<float2*>(out + c*VOL + base) = o;
    }
  } else {
    #pragma unroll
    for (int c = 0; c < COUT; c++){
      float2 o; o.x = r0[c]; o.y = r1[c];
      *reinterpret_cast<float2*>(out + c*VOL + base) = o;
    }
  }
}

// ============================================================================
// Adaptive conv, SMEM-tiled. Weights are per-voxel but channel-INVARIANT:
// C=8 path interleaves the tile as float2 channel-pairs (same 48 KB) and uses
// fma2 — one LDS.64 feeds two channels; each packed weight (mov.b64, hoisted
// once per tap) feeds all 4 channel-pairs. Halves main-loop instruction count
// vs the scalar version at identical crossbar bytes.
// ============================================================================
template<int C, bool TANH>
__global__ void __launch_bounds__(256)
adapt_k(const float* __restrict__ x, const float* __restrict__ w27,
        float* __restrict__ out)
{
  const int tid = threadIdx.x;
  const int h0 = 2*blockIdx.x;
  const int d  = blockIdx.y;
  const int hs = tid >> 7;            // 0/1: which h row
  const int w  = tid & 127;
  const int idx = d*PLANE + (h0+hs)*128 + w;

  if constexpr (C == 8){
    __shared__ float2 tile[48*128];   // [4 cpair][3 d][4 h][128 w] = 48 KB
    // ---- fill: 48 float2-rows; 4 rows per pass, 64 threads per row ----
    {
      const int sub  = tid >> 6;      // 0..3 row-in-pass
      const int lane = tid & 63;      // w-pair index
      #pragma unroll
      for (int it = 0; it < 12; it++){
        const int row = it*4 + sub;               // 0..47
        const int cp  = (row*43) >> 9;            // row/12
        const int rm  = row - cp*12;
        const int di  = rm >> 2;                  // 0..2
        const int hi  = rm & 3;                   // 0..3
        const int dd  = d + di - 1;
        const int hh  = h0 + hi - 1;
        float2 a = make_float2(0.f,0.f), b = make_float2(0.f,0.f);
        if ((unsigned)dd < 128u && (unsigned)hh < 128u){
          const float* p0 = x + (2*cp)*VOL + (dd*128 + hh)*128 + lane*2;
          a = *reinterpret_cast<const float2*>(p0);
          b = *reinterpret_cast<const float2*>(p0 + VOL);
        }
        float4 st = make_float4(a.x, b.x, a.y, b.y);
        *reinterpret_cast<float4*>(tile + row*128 + lane*2) = st;
      }
    }

    float wv[27];
    #pragma unroll
    for (int t = 0; t < 27; t++) wv[t] = __ldg(w27 + t*VOL + idx);

    __syncthreads();

    const bool wa = (w > 0), we = (w < 127);
    u64 acc[4] = {0ull,0ull,0ull,0ull};

    #pragma unroll
    for (int i = 0; i < 3; i++){
      #pragma unroll
      for (int j = 0; j < 3; j++){
        const float2* rp = tile + (i*4 + hs + j)*128 + w;
        #pragma unroll
        for (int k = 0; k < 3; k++){
          const int t = i*9 + j*3 + k;
          const u64 wpk = pack2(wv[t], wv[t]);
          const bool ok = (k==0) ? wa : (k==2) ? we : true;
          #pragma unroll
          for (int cp = 0; cp < 4; cp++){
            float2 v = make_float2(0.f,0.f);
            if (ok) v = rp[cp*1536 + (k-1)];
            fma2(acc[cp], wpk, *reinterpret_cast<const u64*>(&v));
          }
        }
      }
    }

    #pragma unroll
    for (int cp = 0; cp < 4; cp++){
      float r0, r1; unpack2(r0, r1, acc[cp]);
      out[(2*cp  )*VOL + idx] = TANH ? tanhf(r0) : r0;
      out[(2*cp+1)*VOL + idx] = TANH ? tanhf(r1) : r1;
    }
  } else {
    // ---- C == 1 scalar path (6 KB tile) ----
    __shared__ float tile[12*128];
    {
      const int sub  = tid >> 5;      // 0..7
      const int lane = tid & 31;      // float4 column
      #pragma unroll
      for (int it = 0; it < 2; it++){
        const int row = it*8 + sub;
        if (row < 12){
          const int di = row >> 2, hi = row & 3;
          const int dd = d + di - 1, hh = h0 + hi - 1;
          float4 v = make_float4(0.f,0.f,0.f,0.f);
          if ((unsigned)dd < 128u && (unsigned)hh < 128u)
            v = *reinterpret_cast<const float4*>(x + (dd*128 + hh)*128 + lane*4);
          *reinterpret_cast<float4*>(tile + row*128 + lane*4) = v;
        }
      }
    }

    float wv[27];
    #pragma unroll
    for (int t = 0; t < 27; t++) wv[t] = __ldg(w27 + t*VOL + idx);

    __syncthreads();

    const bool wa = (w > 0), we = (w < 127);
    float s0 = 0.f, s1 = 0.f, s2 = 0.f;
    #pragma unroll
    for (int i = 0; i < 3; i++){
      #pragma unroll
      for (int j = 0; j < 3; j++){
        const float* rp = tile + (i*4 + hs + j)*128 + w;
        const int t = i*9 + j*3;
        float va = 0.f, vc = 0.f;
        if (wa) va = rp[-1];
        if (we) vc = rp[ 1];
        s0 = fmaf(wv[t  ], va,    s0);
        s1 = fmaf(wv[t+1], rp[0], s1);
        s2 = fmaf(wv[t+2], vc,    s2);
      }
    }
    float acc = s0 + s1 + s2;
    out[idx] = TANH ? tanhf(acc) : acc;
  }
}

extern "C" void kernel_launch(void* const* d_in, const int* in_sizes, int n_in,
                              void* d_out, int out_size)
{
  const float* x    = (const float*)d_in[0];
  const float* a1w1 = (const float*)d_in[1];
  const float* a1b1 = (const float*)d_in[2];
  const float* a1w2 = (const float*)d_in[3];
  const float* a2w1 = (const float*)d_in[4];
  const float* a2b1 = (const float*)d_in[5];
  const float* a2w2 = (const float*)d_in[6];
  const float* a3w1 = (const float*)d_in[7];
  const float* a3b1 = (const float*)d_in[8];
  const float* a3w2 = (const float*)d_in[9];
  const float* midw = (const float*)d_in[10];
  const float* midb = (const float*)d_in[11];
  const float* outw = (const float*)d_in[12];
  const float* outb = (const float*)d_in[13];
  float* y = (float*)d_out;

  float *H, *A, *W, *F;
  cudaGetSymbolAddress((void**)&H, g_H);
  cudaGetSymbolAddress((void**)&A, g_A);
  cudaGetSymbolAddress((void**)&W, g_W);
  cudaGetSymbolAddress((void**)&F, g_F);

  dim3 gc(64, 128), bc(128);        // conv: h-pair x d; thread = w-pair
  dim3 ga(64, 128), ba(256);        // adapt: h-pair x d; thread = voxel

  // ---- adaptive block 1 (input x) ----
  conv3d_k<8,  true,  false><<<gc,bc>>>(x, a1w1, a1b1, H);     // h1
  conv3d_k<27, false, true ><<<gc,bc>>>(H, a1w2, nullptr, W);  // weight field
  adapt_k<8, false><<<ga,ba>>>(x, W, A);
  adapt_k<8, false><<<ga,ba>>>(A, W, H);
  adapt_k<8, false><<<ga,ba>>>(H, W, A);                       // block1 out = A

  // ---- mid conv ----
  conv3d_k<8, false, false><<<gc,bc>>>(A, midw, midb, H);      // mid = H

  // ---- adaptive block 2 (input mid) ----
  conv3d_k<8,  true,  false><<<gc,bc>>>(H, a2w1, a2b1, A);     // h2
  conv3d_k<27, false, true ><<<gc,bc>>>(A, a2w2, nullptr, W);
  adapt_k<8, false><<<ga,ba>>>(H, W, A);
  adapt_k<8, false><<<ga,ba>>>(A, W, H);
  adapt_k<8, false><<<ga,ba>>>(H, W, A);                       // mid2 = A

  // ---- out conv + adaptive block 3 (weights from mid2, data 1-channel) ----
  conv3d_k<1, false, false><<<gc,bc>>>(A, outw, outb, F);      // final (1ch)
  conv3d_k<8, true,  false><<<gc,bc>>>(A, a3w1, a3b1, H);      // h3 from mid2
  conv3d_k<27, false, true ><<<gc,bc>>>(H, a3w2, nullptr, W);
  adapt_k<1, false><<<ga,ba>>>(F, W, y);
  adapt_k<1, false><<<ga,ba>>>(y, W, F);
  adapt_k<1, true ><<<ga,ba>>>(F, W, y);                       // + tanh
}